// round 14
// baseline (speedup 1.0000x reference)
#include <cuda_runtime.h>
#include <cuda_bf16.h>

#define MAX_NODES 2097152
__device__ float4 g_pred4[MAX_NODES];   // pre-scaled nodal displacements (x*uc, y*uc, th*tc, 0)
__device__ float4 g_Fint4[MAX_NODES];   // accumulated internal forces (w unused)
__device__ double g_sumR;
__device__ double g_sumF;
__device__ unsigned int g_ticket;

// Pass 1 (R10 best): pack+scale pred into float4 AND zero the accumulator.
__global__ void __launch_bounds__(256) pack_kernel(
        const float4* __restrict__ pred4in,
        const float*  __restrict__ pred,
        const float*  __restrict__ u_c,
        const float*  __restrict__ th_c,
        int N) {
    __shared__ float sm[8][96];
    const float uc = __ldg(u_c);
    const float tc = __ldg(th_c);
    const float4 z = make_float4(0.f, 0.f, 0.f, 0.f);

    const int lane = threadIdx.x & 31;
    const int wib  = threadIdx.x >> 5;
    const int gwarp = (blockIdx.x * blockDim.x + threadIdx.x) >> 5;
    const int nwarps = (gridDim.x * blockDim.x) >> 5;

    for (int base = gwarp * 32; base < N; base += nwarps * 32) {
        if (base + 32 <= N) {
            const float4* src = pred4in + (3 * base >> 2);   // base%32==0 -> aligned
            if (lane < 24) {
                ((float4*)sm[wib])[lane] = __ldcs(&src[lane]);
            }
            __syncwarp();
            const float x = sm[wib][3 * lane + 0];
            const float y = sm[wib][3 * lane + 1];
            const float t = sm[wib][3 * lane + 2];
            __syncwarp();
            g_pred4[base + lane] = make_float4(x * uc, y * uc, t * tc, 0.f);
            g_Fint4[base + lane] = z;
        } else {
            const int i = base + lane;
            if (i < N) {
                g_pred4[i] = make_float4(pred[3 * i] * uc, pred[3 * i + 1] * uc,
                                         pred[3 * i + 2] * tc, 0.f);
                g_Fint4[i] = z;
            }
        }
    }
#if __CUDA_ARCH__ >= 900
    cudaTriggerProgrammaticLaunchCompletion();
#endif
}

__device__ __forceinline__ void red_v4(float4* addr, float x, float y, float z, float w) {
    asm volatile("red.global.add.v4.f32 [%0], {%1, %2, %3, %4};"
                 :: "l"(addr), "f"(x), "f"(y), "f"(z), "f"(w) : "memory");
}

// Pass 2: per-element local forces, scatter-add via v4 REDG. 1 elem/thread.
// PDL: streaming operands loaded BEFORE the grid-dependency sync.
__global__ void __launch_bounds__(256) elem_kernel(
        const float* __restrict__ L,
        const float* __restrict__ pE,
        const float* __restrict__ pA,
        const float* __restrict__ pI,
        const float* __restrict__ dirs,
        const int2*  __restrict__ conn,
        int E) {
    const int e = blockIdx.x * blockDim.x + threadIdx.x;

    int2 ab = make_int2(0, 0);
    float c = 0.f, s = 0.f, Le = 1.f, Ee = 0.f, Ae = 0.f, Ie = 0.f;
    if (e < E) {
        ab = __ldcs(&conn[e]);
        c  = __ldcs(&dirs[3 * e + 0]);
        s  = __ldcs(&dirs[3 * e + 2]);
        Le = __ldcs(&L[e]);
        Ee = __ldcs(&pE[e]);
        Ae = __ldcs(&pA[e]);
        Ie = __ldcs(&pI[e]);
    }

#if __CUDA_ARCH__ >= 900
    cudaGridDependencySynchronize();   // pack's stores now visible
    cudaTriggerProgrammaticLaunchCompletion();
#endif
    if (e >= E) return;

    const float EA = Ee * Ae;
    const float EI = Ee * Ie;

    const float4 a = g_pred4[ab.x];
    const float4 b = g_pred4[ab.y];

    const float u_A  =  c * a.x + s * a.y;
    const float w_A  = -s * a.x + c * a.y;
    const float thA  = -a.z;
    const float u_B  =  c * b.x + s * b.y;
    const float w_B  = -s * b.x + c * b.y;
    const float thB  = -b.z;

    const float inv_L = 1.0f / Le;
    const float ea_l  = EA * inv_L;            // AXIAL_WEIGHT = 1
    const float ei_l  = EI * inv_L;
    const float ei_l2 = ei_l * inv_L;
    const float ei_l3 = ei_l2 * inv_L;

    const float dw = w_A - w_B;
    const float f0 = ea_l * (u_A - u_B);
    const float f1 = 12.0f * ei_l3 * dw + 6.0f * ei_l2 * (thA + thB);
    const float f2 = 6.0f * ei_l2 * dw + 4.0f * ei_l * thA + 2.0f * ei_l * thB;
    const float f5 = 6.0f * ei_l2 * dw + 2.0f * ei_l * thA + 4.0f * ei_l * thB;

    const float fAx = c * f0 - s * f1;
    const float fAy = s * f0 + c * f1;

    red_v4(&g_Fint4[ab.x],  fAx,  fAy, -f2, 0.0f);
    red_v4(&g_Fint4[ab.y], -fAx, -fAy, -f5, 0.0f);
}

// Pass 3: SINGLE-PASS node kernel (1 node/thread, no loop).
// ALL independent streaming loads (bc, F_ext) issue before the dependency
// sync -> they overlap elem's atomic drain. Only the Fint read follows.
__global__ void __launch_bounds__(256) node_kernel(
        const float* __restrict__ F_ext,
        const float* __restrict__ bc_disp,
        const float* __restrict__ bc_rot,
        float* __restrict__ out,
        int N) {
    const int i = blockIdx.x * blockDim.x + threadIdx.x;

    float bd = 0.f, br = 0.f, Fe0 = 0.f, Fe1 = 0.f, Fe2 = 0.f;
    if (i < N) {
        bd  = __ldcs(&bc_disp[i]);
        br  = __ldcs(&bc_rot[i]);
        Fe0 = __ldcs(&F_ext[3 * i + 0]);
        Fe1 = __ldcs(&F_ext[3 * i + 1]);
        Fe2 = __ldcs(&F_ext[3 * i + 2]);
    }
#if __CUDA_ARCH__ >= 900
    cudaGridDependencySynchronize();   // elem's REDGs now visible
#endif

    float lr = 0.0f;
    float lf = 0.0f;
    if (i < N) {
        const float md = 1.0f - bd;
        const float mr = 1.0f - br;
        const float4 Fi = __ldcs(&g_Fint4[i]);
        const float R0 = (Fi.x - Fe0) * md;
        const float R1 = (Fi.y - Fe1) * md;
        const float R2 = (Fi.z - Fe2) * mr;
        const float F0 = Fe0 * md;
        const float F1 = Fe1 * md;
        const float F2 = Fe2 * mr;
        lr = R0 * R0 + R1 * R1 + R2 * R2;
        lf = F0 * F0 + F1 * F1 + F2 * F2;
    }

    #pragma unroll
    for (int off = 16; off > 0; off >>= 1) {
        lr += __shfl_down_sync(0xFFFFFFFFu, lr, off);
        lf += __shfl_down_sync(0xFFFFFFFFu, lf, off);
    }

    __shared__ float s_r[8];
    __shared__ float s_f[8];
    const int lane = threadIdx.x & 31;
    const int wid  = threadIdx.x >> 5;
    if (lane == 0) { s_r[wid] = lr; s_f[wid] = lf; }
    __syncthreads();

    __shared__ bool s_last;
    if (wid == 0) {
        lr = (lane < 8) ? s_r[lane] : 0.0f;
        lf = (lane < 8) ? s_f[lane] : 0.0f;
        #pragma unroll
        for (int off = 4; off > 0; off >>= 1) {
            lr += __shfl_down_sync(0xFFFFFFFFu, lr, off);
            lf += __shfl_down_sync(0xFFFFFFFFu, lf, off);
        }
        if (lane == 0) {
            atomicAdd(&g_sumR, (double)lr);
            atomicAdd(&g_sumF, (double)lf);
            __threadfence();
            unsigned int t = atomicAdd(&g_ticket, 1u);
            s_last = (t == (unsigned int)(gridDim.x - 1));
        }
    }
    __syncthreads();

    if (threadIdx.x == 0 && s_last) {
        double f = g_sumF;
        if (f < 1e-30) f = 1e-30;
        out[0] = (float)(g_sumR / f);
        g_sumR = 0.0;
        g_sumF = 0.0;
        __threadfence();
        g_ticket = 0u;
    }
}

extern "C" void kernel_launch(void* const* d_in, const int* in_sizes, int n_in,
                              void* d_out, int out_size) {
    const float* pred   = (const float*)d_in[0];
    const float* u_c    = (const float*)d_in[1];
    const float* th_c   = (const float*)d_in[2];
    const float* L      = (const float*)d_in[3];
    const float* pE     = (const float*)d_in[4];
    const float* pA     = (const float*)d_in[5];
    const float* pI     = (const float*)d_in[6];
    const float* dirs   = (const float*)d_in[7];
    const float* F_ext  = (const float*)d_in[8];
    const float* bcd    = (const float*)d_in[9];
    const float* bcr    = (const float*)d_in[10];
    const int*   conn   = (const int*)d_in[11];

    const int N = in_sizes[0] / 3;
    const int E = in_sizes[3];

    float* out = (float*)d_out;

    // --- pack (R10 config) ---
    {
        int threads = 256;
        int warps_needed = (N + 31) / 32;
        int blocks = (warps_needed + 7) / 8;
        if (blocks > 4096) blocks = 4096;
        pack_kernel<<<blocks, threads>>>((const float4*)pred, pred, u_c, th_c, N);
    }

    cudaLaunchAttribute pdl[1];
    pdl[0].id = cudaLaunchAttributeProgrammaticStreamSerialization;
    pdl[0].val.programmaticStreamSerializationAllowed = 1;

    // --- elem (PDL) ---
    {
        cudaLaunchConfig_t cfg = {};
        cfg.gridDim  = dim3((E + 255) / 256);
        cfg.blockDim = dim3(256);
        cfg.stream   = 0;
        cfg.attrs    = pdl;
        cfg.numAttrs = 1;
        cudaLaunchKernelEx(&cfg, elem_kernel, L, pE, pA, pI, dirs,
                           (const int2*)conn, E);
    }

    // --- node (PDL, single-pass) ---
    {
        cudaLaunchConfig_t cfg = {};
        cfg.gridDim  = dim3((N + 255) / 256);
        cfg.blockDim = dim3(256);
        cfg.stream   = 0;
        cfg.attrs    = pdl;
        cfg.numAttrs = 1;
        cudaLaunchKernelEx(&cfg, node_kernel, F_ext, bcd, bcr, out, N);
    }
}

// round 15
// speedup vs baseline: 1.0422x; 1.0422x over previous
#include <cuda_runtime.h>
#include <cuda_bf16.h>

#define MAX_NODES 2097152
__device__ float4 g_pred4[MAX_NODES];   // pre-scaled nodal displacements (x*uc, y*uc, th*tc, 0)
__device__ float4 g_Fint4[MAX_NODES];   // accumulated internal forces (w unused)
__device__ double g_sumR;
__device__ double g_sumF;
__device__ unsigned int g_ticket;

// Pass 1: pack+scale pred into float4 AND zero the accumulator.
// Warp-coalesced: 24 lanes LDG.128 the 96 floats for 32 nodes, stride-3 smem
// transpose (conflict-free since gcd(3,32)=1), 1 node/thread float4 stores.
// Writing the Fint zeros here keeps those lines L2-resident for elem's atomics.
__global__ void __launch_bounds__(256) pack_kernel(
        const float4* __restrict__ pred4in,
        const float*  __restrict__ pred,
        const float*  __restrict__ u_c,
        const float*  __restrict__ th_c,
        int N) {
    __shared__ float sm[8][96];
    const float uc = __ldg(u_c);
    const float tc = __ldg(th_c);
    const float4 z = make_float4(0.f, 0.f, 0.f, 0.f);

    const int lane = threadIdx.x & 31;
    const int wib  = threadIdx.x >> 5;
    const int gwarp = (blockIdx.x * blockDim.x + threadIdx.x) >> 5;
    const int nwarps = (gridDim.x * blockDim.x) >> 5;

    for (int base = gwarp * 32; base < N; base += nwarps * 32) {
        if (base + 32 <= N) {
            const float4* src = pred4in + (3 * base >> 2);   // base%32==0 -> aligned
            if (lane < 24) {
                ((float4*)sm[wib])[lane] = __ldcs(&src[lane]);
            }
            __syncwarp();
            const float x = sm[wib][3 * lane + 0];
            const float y = sm[wib][3 * lane + 1];
            const float t = sm[wib][3 * lane + 2];
            __syncwarp();
            g_pred4[base + lane] = make_float4(x * uc, y * uc, t * tc, 0.f);
            g_Fint4[base + lane] = z;
        } else {
            const int i = base + lane;
            if (i < N) {
                g_pred4[i] = make_float4(pred[3 * i] * uc, pred[3 * i + 1] * uc,
                                         pred[3 * i + 2] * tc, 0.f);
                g_Fint4[i] = z;
            }
        }
    }
#if __CUDA_ARCH__ >= 900
    cudaTriggerProgrammaticLaunchCompletion();
#endif
}

__device__ __forceinline__ void red_v4(float4* addr, float x, float y, float z, float w) {
    asm volatile("red.global.add.v4.f32 [%0], {%1, %2, %3, %4};"
                 :: "l"(addr), "f"(x), "f"(y), "f"(z), "f"(w) : "memory");
}

// Pass 2: per-element local forces, scatter-add via v4 REDG. 1 elem/thread.
// PDL: streaming operands loaded BEFORE the grid-dependency sync (overlap with
// pack's drain); gathers + REDGs (which touch pack's output) after it.
__global__ void __launch_bounds__(256) elem_kernel(
        const float* __restrict__ L,
        const float* __restrict__ pE,
        const float* __restrict__ pA,
        const float* __restrict__ pI,
        const float* __restrict__ dirs,
        const int2*  __restrict__ conn,
        int E) {
    const int e = blockIdx.x * blockDim.x + threadIdx.x;

    int2 ab = make_int2(0, 0);
    float c = 0.f, s = 0.f, Le = 1.f, Ee = 0.f, Ae = 0.f, Ie = 0.f;
    if (e < E) {
        ab = __ldcs(&conn[e]);
        c  = __ldcs(&dirs[3 * e + 0]);
        s  = __ldcs(&dirs[3 * e + 2]);
        Le = __ldcs(&L[e]);
        Ee = __ldcs(&pE[e]);
        Ae = __ldcs(&pA[e]);
        Ie = __ldcs(&pI[e]);
    }

#if __CUDA_ARCH__ >= 900
    cudaGridDependencySynchronize();   // pack's stores now visible
#endif
    if (e >= E) return;

    const float EA = Ee * Ae;
    const float EI = Ee * Ie;

    const float4 a = g_pred4[ab.x];
    const float4 b = g_pred4[ab.y];

    const float u_A  =  c * a.x + s * a.y;
    const float w_A  = -s * a.x + c * a.y;
    const float thA  = -a.z;
    const float u_B  =  c * b.x + s * b.y;
    const float w_B  = -s * b.x + c * b.y;
    const float thB  = -b.z;

    const float inv_L = 1.0f / Le;
    const float ea_l  = EA * inv_L;            // AXIAL_WEIGHT = 1
    const float ei_l  = EI * inv_L;
    const float ei_l2 = ei_l * inv_L;
    const float ei_l3 = ei_l2 * inv_L;

    const float dw = w_A - w_B;
    const float f0 = ea_l * (u_A - u_B);
    const float f1 = 12.0f * ei_l3 * dw + 6.0f * ei_l2 * (thA + thB);
    const float f2 = 6.0f * ei_l2 * dw + 4.0f * ei_l * thA + 2.0f * ei_l * thB;
    const float f5 = 6.0f * ei_l2 * dw + 2.0f * ei_l * thA + 4.0f * ei_l * thB;

    const float fAx = c * f0 - s * f1;
    const float fAy = s * f0 + c * f1;

    red_v4(&g_Fint4[ab.x],  fAx,  fAy, -f2, 0.0f);
    red_v4(&g_Fint4[ab.y], -fAx, -fAy, -f5, 0.0f);
}

// Pass 3: grid-stride masked residual norm, fused finalize + self-reset.
// PDL: first iteration's independent streams loaded before the sync.
__global__ void node_kernel(const float* __restrict__ F_ext,
                            const float* __restrict__ bc_disp,
                            const float* __restrict__ bc_rot,
                            float* __restrict__ out,
                            int N) {
    const int i0 = blockIdx.x * blockDim.x + threadIdx.x;
    const int stride = gridDim.x * blockDim.x;

    float pmd = 0.f, pmr = 0.f, pe0 = 0.f, pe1 = 0.f, pe2 = 0.f;
    if (i0 < N) {
        pmd = __ldcs(&bc_disp[i0]);
        pmr = __ldcs(&bc_rot[i0]);
        pe0 = __ldcs(&F_ext[3 * i0 + 0]);
        pe1 = __ldcs(&F_ext[3 * i0 + 1]);
        pe2 = __ldcs(&F_ext[3 * i0 + 2]);
    }
#if __CUDA_ARCH__ >= 900
    cudaGridDependencySynchronize();   // elem's REDGs now visible
#endif

    float lr = 0.0f;
    float lf = 0.0f;
    bool first = true;
    for (int i = i0; i < N; i += stride) {
        float md, mr, Fe0, Fe1, Fe2;
        if (first) {
            md = 1.0f - pmd; mr = 1.0f - pmr;
            Fe0 = pe0; Fe1 = pe1; Fe2 = pe2;
            first = false;
        } else {
            md = 1.0f - __ldcs(&bc_disp[i]);
            mr = 1.0f - __ldcs(&bc_rot[i]);
            Fe0 = __ldcs(&F_ext[3 * i + 0]);
            Fe1 = __ldcs(&F_ext[3 * i + 1]);
            Fe2 = __ldcs(&F_ext[3 * i + 2]);
        }
        const float4 Fi = __ldcs(&g_Fint4[i]);
        const float R0 = (Fi.x - Fe0) * md;
        const float R1 = (Fi.y - Fe1) * md;
        const float R2 = (Fi.z - Fe2) * mr;
        const float F0 = Fe0 * md;
        const float F1 = Fe1 * md;
        const float F2 = Fe2 * mr;
        lr += R0 * R0 + R1 * R1 + R2 * R2;
        lf += F0 * F0 + F1 * F1 + F2 * F2;
    }

    #pragma unroll
    for (int off = 16; off > 0; off >>= 1) {
        lr += __shfl_down_sync(0xFFFFFFFFu, lr, off);
        lf += __shfl_down_sync(0xFFFFFFFFu, lf, off);
    }

    __shared__ float s_r[32];
    __shared__ float s_f[32];
    const int lane = threadIdx.x & 31;
    const int wid  = threadIdx.x >> 5;
    if (lane == 0) { s_r[wid] = lr; s_f[wid] = lf; }
    __syncthreads();

    __shared__ bool s_last;
    if (wid == 0) {
        const int nwarps = (blockDim.x + 31) >> 5;
        lr = (lane < nwarps) ? s_r[lane] : 0.0f;
        lf = (lane < nwarps) ? s_f[lane] : 0.0f;
        #pragma unroll
        for (int off = 16; off > 0; off >>= 1) {
            lr += __shfl_down_sync(0xFFFFFFFFu, lr, off);
            lf += __shfl_down_sync(0xFFFFFFFFu, lf, off);
        }
        if (lane == 0) {
            atomicAdd(&g_sumR, (double)lr);
            atomicAdd(&g_sumF, (double)lf);
            __threadfence();
            unsigned int t = atomicAdd(&g_ticket, 1u);
            s_last = (t == (unsigned int)(gridDim.x - 1));
        }
    }
    __syncthreads();

    if (threadIdx.x == 0 && s_last) {
        double f = g_sumF;
        if (f < 1e-30) f = 1e-30;
        out[0] = (float)(g_sumR / f);
        g_sumR = 0.0;
        g_sumF = 0.0;
        __threadfence();
        g_ticket = 0u;
    }
}

extern "C" void kernel_launch(void* const* d_in, const int* in_sizes, int n_in,
                              void* d_out, int out_size) {
    const float* pred   = (const float*)d_in[0];
    const float* u_c    = (const float*)d_in[1];
    const float* th_c   = (const float*)d_in[2];
    const float* L      = (const float*)d_in[3];
    const float* pE     = (const float*)d_in[4];
    const float* pA     = (const float*)d_in[5];
    const float* pI     = (const float*)d_in[6];
    const float* dirs   = (const float*)d_in[7];
    const float* F_ext  = (const float*)d_in[8];
    const float* bcd    = (const float*)d_in[9];
    const float* bcr    = (const float*)d_in[10];
    const int*   conn   = (const int*)d_in[11];

    const int N = in_sizes[0] / 3;
    const int E = in_sizes[3];

    float* out = (float*)d_out;

    // --- pack (R10 config) ---
    {
        int threads = 256;
        int warps_needed = (N + 31) / 32;
        int blocks = (warps_needed + 7) / 8;
        if (blocks > 4096) blocks = 4096;
        pack_kernel<<<blocks, threads>>>((const float4*)pred, pred, u_c, th_c, N);
    }

    cudaLaunchAttribute pdl[1];
    pdl[0].id = cudaLaunchAttributeProgrammaticStreamSerialization;
    pdl[0].val.programmaticStreamSerializationAllowed = 1;

    // --- elem (PDL) ---
    {
        cudaLaunchConfig_t cfg = {};
        cfg.gridDim  = dim3((E + 255) / 256);
        cfg.blockDim = dim3(256);
        cfg.stream   = 0;
        cfg.attrs    = pdl;
        cfg.numAttrs = 1;
        cudaLaunchKernelEx(&cfg, elem_kernel, L, pE, pA, pI, dirs,
                           (const int2*)conn, E);
    }

    // --- node (PDL, grid-stride 2368 blocks) ---
    {
        int threads = 256;
        int blocks = (N + threads - 1) / threads;
        if (blocks > 2368) blocks = 2368;
        cudaLaunchConfig_t cfg = {};
        cfg.gridDim  = dim3(blocks);
        cfg.blockDim = dim3(threads);
        cfg.stream   = 0;
        cfg.attrs    = pdl;
        cfg.numAttrs = 1;
        cudaLaunchKernelEx(&cfg, node_kernel, F_ext, bcd, bcr, out, N);
    }
}

// round 16
// speedup vs baseline: 1.0435x; 1.0012x over previous
#include <cuda_runtime.h>
#include <cuda_bf16.h>

#define MAX_NODES 2097152
__device__ float4 g_pred4[MAX_NODES];   // pre-scaled nodal displacements (x*uc, y*uc, th*tc, 0)
__device__ float4 g_Fint4[MAX_NODES];   // accumulated internal forces (w unused)
__device__ double g_sumR;
__device__ double g_sumF;
__device__ unsigned int g_ticket;

// Pass 1: pack+scale pred into float4 AND zero the accumulator.
// Warp-coalesced: 24 lanes LDG.128 the 96 floats for 32 nodes, stride-3 smem
// transpose (conflict-free since gcd(3,32)=1), 1 node/thread float4 stores.
__global__ void __launch_bounds__(256) pack_kernel(
        const float4* __restrict__ pred4in,
        const float*  __restrict__ pred,
        const float*  __restrict__ u_c,
        const float*  __restrict__ th_c,
        int N) {
    __shared__ float sm[8][96];
    const float uc = __ldg(u_c);
    const float tc = __ldg(th_c);
    const float4 z = make_float4(0.f, 0.f, 0.f, 0.f);

    const int lane = threadIdx.x & 31;
    const int wib  = threadIdx.x >> 5;
    const int gwarp = (blockIdx.x * blockDim.x + threadIdx.x) >> 5;
    const int nwarps = (gridDim.x * blockDim.x) >> 5;

    for (int base = gwarp * 32; base < N; base += nwarps * 32) {
        if (base + 32 <= N) {
            const float4* src = pred4in + (3 * base >> 2);   // base%32==0 -> aligned
            if (lane < 24) {
                ((float4*)sm[wib])[lane] = __ldcs(&src[lane]);
            }
            __syncwarp();
            const float x = sm[wib][3 * lane + 0];
            const float y = sm[wib][3 * lane + 1];
            const float t = sm[wib][3 * lane + 2];
            __syncwarp();
            g_pred4[base + lane] = make_float4(x * uc, y * uc, t * tc, 0.f);
            g_Fint4[base + lane] = z;
        } else {
            const int i = base + lane;
            if (i < N) {
                g_pred4[i] = make_float4(pred[3 * i] * uc, pred[3 * i + 1] * uc,
                                         pred[3 * i + 2] * tc, 0.f);
                g_Fint4[i] = z;
            }
        }
    }
#if __CUDA_ARCH__ >= 900
    cudaTriggerProgrammaticLaunchCompletion();
#endif
}

__device__ __forceinline__ void red_v4(float4* addr, float x, float y, float z, float w) {
    asm volatile("red.global.add.v4.f32 [%0], {%1, %2, %3, %4};"
                 :: "l"(addr), "f"(x), "f"(y), "f"(z), "f"(w) : "memory");
}

// Pass 2: per-element local forces, scatter-add via v4 REDG. 1 elem/thread.
// 128-thread blocks: finer CTA granularity -> smaller per-CTA REDG-drain
// coupling and better wave balance. Per-warp behavior unchanged.
__global__ void __launch_bounds__(128) elem_kernel(
        const float* __restrict__ L,
        const float* __restrict__ pE,
        const float* __restrict__ pA,
        const float* __restrict__ pI,
        const float* __restrict__ dirs,
        const int2*  __restrict__ conn,
        int E) {
    const int e = blockIdx.x * blockDim.x + threadIdx.x;

    int2 ab = make_int2(0, 0);
    float c = 0.f, s = 0.f, Le = 1.f, Ee = 0.f, Ae = 0.f, Ie = 0.f;
    if (e < E) {
        ab = __ldcs(&conn[e]);
        c  = __ldcs(&dirs[3 * e + 0]);
        s  = __ldcs(&dirs[3 * e + 2]);
        Le = __ldcs(&L[e]);
        Ee = __ldcs(&pE[e]);
        Ae = __ldcs(&pA[e]);
        Ie = __ldcs(&pI[e]);
    }

#if __CUDA_ARCH__ >= 900
    cudaGridDependencySynchronize();   // pack's stores now visible
#endif
    if (e >= E) return;

    const float EA = Ee * Ae;
    const float EI = Ee * Ie;

    const float4 a = g_pred4[ab.x];
    const float4 b = g_pred4[ab.y];

    const float u_A  =  c * a.x + s * a.y;
    const float w_A  = -s * a.x + c * a.y;
    const float thA  = -a.z;
    const float u_B  =  c * b.x + s * b.y;
    const float w_B  = -s * b.x + c * b.y;
    const float thB  = -b.z;

    const float inv_L = 1.0f / Le;
    const float ea_l  = EA * inv_L;            // AXIAL_WEIGHT = 1
    const float ei_l  = EI * inv_L;
    const float ei_l2 = ei_l * inv_L;
    const float ei_l3 = ei_l2 * inv_L;

    const float dw = w_A - w_B;
    const float f0 = ea_l * (u_A - u_B);
    const float f1 = 12.0f * ei_l3 * dw + 6.0f * ei_l2 * (thA + thB);
    const float f2 = 6.0f * ei_l2 * dw + 4.0f * ei_l * thA + 2.0f * ei_l * thB;
    const float f5 = 6.0f * ei_l2 * dw + 2.0f * ei_l * thA + 4.0f * ei_l * thB;

    const float fAx = c * f0 - s * f1;
    const float fAy = s * f0 + c * f1;

    red_v4(&g_Fint4[ab.x],  fAx,  fAy, -f2, 0.0f);
    red_v4(&g_Fint4[ab.y], -fAx, -fAy, -f5, 0.0f);
}

// Pass 3: grid-stride masked residual norm, fused finalize + self-reset.
__global__ void node_kernel(const float* __restrict__ F_ext,
                            const float* __restrict__ bc_disp,
                            const float* __restrict__ bc_rot,
                            float* __restrict__ out,
                            int N) {
    const int i0 = blockIdx.x * blockDim.x + threadIdx.x;
    const int stride = gridDim.x * blockDim.x;

    float pmd = 0.f, pmr = 0.f, pe0 = 0.f, pe1 = 0.f, pe2 = 0.f;
    if (i0 < N) {
        pmd = __ldcs(&bc_disp[i0]);
        pmr = __ldcs(&bc_rot[i0]);
        pe0 = __ldcs(&F_ext[3 * i0 + 0]);
        pe1 = __ldcs(&F_ext[3 * i0 + 1]);
        pe2 = __ldcs(&F_ext[3 * i0 + 2]);
    }
#if __CUDA_ARCH__ >= 900
    cudaGridDependencySynchronize();   // elem's REDGs now visible
#endif

    float lr = 0.0f;
    float lf = 0.0f;
    bool first = true;
    for (int i = i0; i < N; i += stride) {
        float md, mr, Fe0, Fe1, Fe2;
        if (first) {
            md = 1.0f - pmd; mr = 1.0f - pmr;
            Fe0 = pe0; Fe1 = pe1; Fe2 = pe2;
            first = false;
        } else {
            md = 1.0f - __ldcs(&bc_disp[i]);
            mr = 1.0f - __ldcs(&bc_rot[i]);
            Fe0 = __ldcs(&F_ext[3 * i + 0]);
            Fe1 = __ldcs(&F_ext[3 * i + 1]);
            Fe2 = __ldcs(&F_ext[3 * i + 2]);
        }
        const float4 Fi = __ldcs(&g_Fint4[i]);
        const float R0 = (Fi.x - Fe0) * md;
        const float R1 = (Fi.y - Fe1) * md;
        const float R2 = (Fi.z - Fe2) * mr;
        const float F0 = Fe0 * md;
        const float F1 = Fe1 * md;
        const float F2 = Fe2 * mr;
        lr += R0 * R0 + R1 * R1 + R2 * R2;
        lf += F0 * F0 + F1 * F1 + F2 * F2;
    }

    #pragma unroll
    for (int off = 16; off > 0; off >>= 1) {
        lr += __shfl_down_sync(0xFFFFFFFFu, lr, off);
        lf += __shfl_down_sync(0xFFFFFFFFu, lf, off);
    }

    __shared__ float s_r[32];
    __shared__ float s_f[32];
    const int lane = threadIdx.x & 31;
    const int wid  = threadIdx.x >> 5;
    if (lane == 0) { s_r[wid] = lr; s_f[wid] = lf; }
    __syncthreads();

    __shared__ bool s_last;
    if (wid == 0) {
        const int nwarps = (blockDim.x + 31) >> 5;
        lr = (lane < nwarps) ? s_r[lane] : 0.0f;
        lf = (lane < nwarps) ? s_f[lane] : 0.0f;
        #pragma unroll
        for (int off = 16; off > 0; off >>= 1) {
            lr += __shfl_down_sync(0xFFFFFFFFu, lr, off);
            lf += __shfl_down_sync(0xFFFFFFFFu, lf, off);
        }
        if (lane == 0) {
            atomicAdd(&g_sumR, (double)lr);
            atomicAdd(&g_sumF, (double)lf);
            __threadfence();
            unsigned int t = atomicAdd(&g_ticket, 1u);
            s_last = (t == (unsigned int)(gridDim.x - 1));
        }
    }
    __syncthreads();

    if (threadIdx.x == 0 && s_last) {
        double f = g_sumF;
        if (f < 1e-30) f = 1e-30;
        out[0] = (float)(g_sumR / f);
        g_sumR = 0.0;
        g_sumF = 0.0;
        __threadfence();
        g_ticket = 0u;
    }
}

extern "C" void kernel_launch(void* const* d_in, const int* in_sizes, int n_in,
                              void* d_out, int out_size) {
    const float* pred   = (const float*)d_in[0];
    const float* u_c    = (const float*)d_in[1];
    const float* th_c   = (const float*)d_in[2];
    const float* L      = (const float*)d_in[3];
    const float* pE     = (const float*)d_in[4];
    const float* pA     = (const float*)d_in[5];
    const float* pI     = (const float*)d_in[6];
    const float* dirs   = (const float*)d_in[7];
    const float* F_ext  = (const float*)d_in[8];
    const float* bcd    = (const float*)d_in[9];
    const float* bcr    = (const float*)d_in[10];
    const int*   conn   = (const int*)d_in[11];

    const int N = in_sizes[0] / 3;
    const int E = in_sizes[3];

    float* out = (float*)d_out;

    // --- pack (R10 config) ---
    {
        int threads = 256;
        int warps_needed = (N + 31) / 32;
        int blocks = (warps_needed + 7) / 8;
        if (blocks > 4096) blocks = 4096;
        pack_kernel<<<blocks, threads>>>((const float4*)pred, pred, u_c, th_c, N);
    }

    cudaLaunchAttribute pdl[1];
    pdl[0].id = cudaLaunchAttributeProgrammaticStreamSerialization;
    pdl[0].val.programmaticStreamSerializationAllowed = 1;

    // --- elem (PDL, 128-thread blocks) ---
    {
        cudaLaunchConfig_t cfg = {};
        cfg.gridDim  = dim3((E + 127) / 128);
        cfg.blockDim = dim3(128);
        cfg.stream   = 0;
        cfg.attrs    = pdl;
        cfg.numAttrs = 1;
        cudaLaunchKernelEx(&cfg, elem_kernel, L, pE, pA, pI, dirs,
                           (const int2*)conn, E);
    }

    // --- node (PDL, grid-stride 2368 blocks) ---
    {
        int threads = 256;
        int blocks = (N + threads - 1) / threads;
        if (blocks > 2368) blocks = 2368;
        cudaLaunchConfig_t cfg = {};
        cfg.gridDim  = dim3(blocks);
        cfg.blockDim = dim3(threads);
        cfg.stream   = 0;
        cfg.attrs    = pdl;
        cfg.numAttrs = 1;
        cudaLaunchKernelEx(&cfg, node_kernel, F_ext, bcd, bcr, out, N);
    }
}